// round 10
// baseline (speedup 1.0000x reference)
#include <cuda_runtime.h>
#include <cstdint>

#define L2E 1.4426950408889634f
typedef unsigned long long ull;

// Scratch (static device globals — no runtime allocation)
__device__ float g_P2[8 * 64 * 1024];   // split-K partials of relu(h1)@W2
__device__ float g_P3[8 * 64 * 512];    // split-K partials of relu(h2)@W3

// Grid-barrier state (returns to all-zero at end of every launch)
__device__ unsigned g_cnt = 0, g_exit = 0;

// ---- packed f32x2 helpers ---------------------------------------------------
__device__ __forceinline__ ull pk2(float lo, float hi) {
    ull r; asm("mov.b64 %0, {%1, %2};" : "=l"(r) : "f"(lo), "f"(hi)); return r;
}
__device__ __forceinline__ void upk2(float& lo, float& hi, ull v) {
    asm("mov.b64 {%0, %1}, %2;" : "=f"(lo), "=f"(hi) : "l"(v));
}
__device__ __forceinline__ ull fma2(ull a, ull b, ull c) {
    ull d; asm("fma.rn.f32x2 %0, %1, %2, %3;" : "=l"(d) : "l"(a), "l"(b), "l"(c)); return d;
}

// ---- software grid barrier (128 blocks, trivially co-resident) --------------
__device__ __forceinline__ void grid_bar128() {
    __syncthreads();
    if (threadIdx.x == 0) {
        __threadfence();
        atomicAdd(&g_cnt, 1u);
        while (*(volatile unsigned*)&g_cnt < 128u) __nanosleep(40);
        __threadfence();
        unsigned e = atomicAdd(&g_exit, 1u);
        if (e == 127u) {                 // last exiter: everyone left the spin
            g_cnt = 0; __threadfence(); g_exit = 0;
        }
    }
    __syncthreads();
}

// ---------------------------------------------------------------------------
// gemm_compute: C[64x32] = A[64 x KS] (stride lda, smem OR global) @
//               W[k0.., n0..] (+bias, relu) -> dst[.., dn0..] (stride ldd).
// W double-buffered from global in 32-k chunks. 256 threads.
// ---------------------------------------------------------------------------
__device__ void gemm_compute(
    const float* A, int lda, int KS,
    const float* __restrict__ W, int N, int n0, int k0,
    float (*Ws)[32][32],
    const float* __restrict__ bias, int do_relu,
    float* dst, int ldd, int dn0)
{
    const int tid = threadIdx.x;
    const int iw = tid >> 3, nn = (tid & 7) * 4;
    {
        float4 w = *(const float4*)(W + (size_t)(k0 + iw) * N + n0 + nn);
        *(float4*)&Ws[0][iw][nn] = w;
    }
    __syncthreads();

    const int n  = tid & 31;
    const int mb = (tid >> 5) * 8;
    ull acc2[8] = {0,0,0,0,0,0,0,0};

    const int NC = KS / 32;
    for (int c = 0; c < NC; c++) {
        if (c + 1 < NC) {
            float4 w = *(const float4*)(W + (size_t)(k0 + (c+1)*32 + iw) * N + n0 + nn);
            *(float4*)&Ws[(c + 1) & 1][iw][nn] = w;
        }
        const float* wsb = &Ws[c & 1][0][0];
        const int kc = c * 32;
        #pragma unroll
        for (int k = 0; k < 32; k += 4) {
            float w0 = wsb[(k+0)*32 + n], w1 = wsb[(k+1)*32 + n];
            float w2 = wsb[(k+2)*32 + n], w3 = wsb[(k+3)*32 + n];
            ull wA = pk2(w0, w1), wB = pk2(w2, w3);
            #pragma unroll
            for (int q = 0; q < 8; q++) {
                ulonglong2 av = *(const ulonglong2*)(A + (size_t)(mb + q) * lda + kc + k);
                acc2[q] = fma2(av.x, wA, acc2[q]);
                acc2[q] = fma2(av.y, wB, acc2[q]);
            }
        }
        __syncthreads();
    }

    #pragma unroll
    for (int q = 0; q < 8; q++) {
        float lo, hi; upk2(lo, hi, acc2[q]);
        float v = lo + hi;
        if (bias) v += bias[n0 + n];
        if (do_relu) v = fmaxf(v, 0.f);
        dst[(size_t)(mb + q) * ldd + dn0 + n] = v;
    }
}

// ---------------------------------------------------------------------------
// Persistent 2-phase MLP (128 blocks, ONE grid barrier).
// Phase A (block = {ks 0..7} x {np 0..15}):
//   h1s[64x64] = relu(f @ W1[:, ks*64..] + b1)      (computed redundantly)
//   P2[ks][:, np*64..+64] = h1s @ W2[ks*64..+64, np*64..]
// Phase B (block = {ks3 0..7} x {nt 0..15}):
//   A = relu(b2 + sum_p P2[p])[:, ks3*128..+128]
//   P3[ks3][:, nt*32..+32] = A @ W3[ks3*128.., nt*32..]
// ---------------------------------------------------------------------------
__global__ void __launch_bounds__(256) mlp_fused(
    const float* __restrict__ f,
    const float* __restrict__ W1, const float* __restrict__ b1,
    const float* __restrict__ W2, const float* __restrict__ b2,
    const float* __restrict__ W3)
{
    __shared__ float As[64 * 128];        // phase A: h1s uses first 64*64
    __shared__ float Ws[2][32][32];

    const int blk = blockIdx.x;
    const int tid = threadIdx.x;

    // ---- Phase A ----
    {
        const int ks = blk & 7;          // K-slice of layer 2 (h1 cols ks*64..)
        const int np = blk >> 3;         // output-col pair of layer 2
        float* h1s = As;                 // 64 x 64, lda 64

        // step 1: h1s = relu(f @ W1[:, ks*64 .. +64) + b1)   (A = f, global, lda 128)
        gemm_compute(f, 128, 128, W1, 512, ks * 64,      0, Ws, b1, 1, h1s, 64, 0);
        gemm_compute(f, 128, 128, W1, 512, ks * 64 + 32, 0, Ws, b1, 1, h1s, 64, 32);

        // step 2: P2 partial = h1s @ W2[ks*64 .. , np*64 ..]
        float* p2 = g_P2 + (size_t)ks * 64 * 1024;
        gemm_compute(h1s, 64, 64, W2, 1024, np * 64,      ks * 64, Ws, nullptr, 0, p2, 1024, np * 64);
        gemm_compute(h1s, 64, 64, W2, 1024, np * 64 + 32, ks * 64, Ws, nullptr, 0, p2, 1024, np * 64 + 32);
    }

    grid_bar128();

    // ---- Phase B ----
    {
        const int ks3 = blk & 7;         // K-slice of layer 3 (h2 cols ks3*128..)
        const int nt  = blk >> 3;        // output tile (32 cols)

        // stage A = relu(b2 + sum_p P2[p])[:, ks3*128 .. +128)
        for (int e = tid; e < 64 * 32; e += 256) {   // 64 rows x 32 float4
            int m = e >> 5, kq = e & 31;
            int k = ks3 * 128 + 4 * kq;
            float4 v = *(const float4*)(b2 + k);
            #pragma unroll
            for (int p = 0; p < 8; p++) {
                float4 w = *(const float4*)(g_P2 + (size_t)p * 64 * 1024 + (size_t)m * 1024 + k);
                v.x += w.x; v.y += w.y; v.z += w.z; v.w += w.w;
            }
            v.x = fmaxf(v.x, 0.f); v.y = fmaxf(v.y, 0.f);
            v.z = fmaxf(v.z, 0.f); v.w = fmaxf(v.w, 0.f);
            *(float4*)&As[m * 128 + 4 * kq] = v;
        }
        // gemm_compute's first internal __syncthreads orders the staging.
        gemm_compute(As, 128, 128, W3, 512, nt * 32, ks3 * 128, Ws, nullptr, 0,
                     g_P3 + (size_t)ks3 * 64 * 512, 512, nt * 32);
    }
}

// ---------------------------------------------------------------------------
// Einsum: E=8 elements/thread (4 f32x2 pairs) — coefficient broadcasts
// amortized over 8 elements inside each warp; ILP hides latency.
// Grid (4, 64), block 128 (4 warps; each warp owns 256 elems).
// ---------------------------------------------------------------------------
__global__ void __launch_bounds__(128) subspace_einsum(
    const float* __restrict__ t,
    const float* __restrict__ mu, const float* __restrict__ alpha,
    const float* __restrict__ beta, const float* __restrict__ gamma,
    const float* __restrict__ b3,
    float* __restrict__ out)
{
    __shared__ float4 s_c1[64];      // (p,p,q,q)
    __shared__ float4 s_c2[64];      // (r,r,beta,beta)
    __shared__ float2 s_c3[64];      // (gamma,gamma)
    __shared__ float4 s_we[64];      // omega even rows (w0..w3) non-dup
    __shared__ float4 s_wo[64];      // omega odd rows

    const int tid  = threadIdx.x;
    const int b    = blockIdx.y;

    if (tid < 64) {
        float al = alpha[tid], m = mu[tid];
        float a2 = al * al * L2E;
        s_c1[tid] = make_float4(-a2, -a2, 2.f * a2 * m, 2.f * a2 * m);
        float r = -a2 * m * m, be = beta[tid];
        s_c2[tid] = make_float4(r, r, be, be);
        float ga = gamma[tid];
        s_c3[tid] = make_float2(ga, ga);
    }
    for (int j = tid; j < 512; j += 128) {
        float v = b3[j];
        #pragma unroll
        for (int p = 0; p < 8; p++)
            v += g_P3[(size_t)p * 64 * 512 + (size_t)b * 512 + j];
        int row = j >> 2, r = j & 3;
        int nb = row & 63;
        float* dst = (row < 64) ? (float*)&s_we[nb] : (float*)&s_wo[nb];
        dst[r] = v;
    }
    __syncthreads();

    const float* tb = t + (size_t)b * 4096;
    const int sidx = blockIdx.x * 1024 + (tid >> 5) * 256 + (tid & 31);

    // 4 pairs: pair p covers elems (sidx + 64p, sidx + 64p + 32)
    ull tt[4], tq[4];
    #pragma unroll
    for (int p = 0; p < 4; p++) {
        float ta = tb[sidx + 64 * p], tbv = tb[sidx + 64 * p + 32];
        tt[p] = pk2(ta, tbv);
        tq[p] = pk2(ta * ta, tbv * tbv);
    }

    // acc[p*8 + 0..3] = elemA {(r0,r1)e,(r2,r3)e,(r0,r1)o,(r2,r3)o}; +4..7 elemB
    ull acc[32];
    #pragma unroll
    for (int j = 0; j < 32; j++) acc[j] = 0ull;

    #pragma unroll 2
    for (int nb = 0; nb < 64; nb++) {
        ulonglong2 c1 = *(const ulonglong2*)&s_c1[nb];  // (p,p)(q,q)
        ulonglong2 c2 = *(const ulonglong2*)&s_c2[nb];  // (r,r)(b,b)
        ull gg = *(const ull*)&s_c3[nb];                // (g,g)
        ulonglong2 we = *(const ulonglong2*)&s_we[nb];  // (w0,w1)(w2,w3)
        ulonglong2 wo = *(const ulonglong2*)&s_wo[nb];

        #pragma unroll
        for (int p = 0; p < 4; p++) {
            ull a = fma2(c1.x, tq[p], fma2(c1.y, tt[p], c2.x));
            float a0, a1; upk2(a0, a1, a);
            float e0, e1;
            asm("ex2.approx.f32 %0, %1;" : "=f"(e0) : "f"(a0));
            asm("ex2.approx.f32 %0, %1;" : "=f"(e1) : "f"(a1));

            ull ca = fma2(c2.y, tt[p], gg);
            float c0, c1f; upk2(c0, c1f, ca);
            float hA = e0 * __cosf(c0);
            float hB = e1 * __cosf(c1f);
            ull hhA = pk2(hA, hA), hhB = pk2(hB, hB);

            ull* aA = acc + p * 8;
            aA[0] = fma2(hhA, we.x, aA[0]);
            aA[1] = fma2(hhA, we.y, aA[1]);
            aA[2] = fma2(hhA, wo.x, aA[2]);
            aA[3] = fma2(hhA, wo.y, aA[3]);
            aA[4] = fma2(hhB, we.x, aA[4]);
            aA[5] = fma2(hhB, we.y, aA[5]);
            aA[6] = fma2(hhB, wo.x, aA[6]);
            aA[7] = fma2(hhB, wo.y, aA[7]);
        }
    }

    float* ob = out + (size_t)b * 32768;
    #pragma unroll
    for (int p = 0; p < 4; p++) {
        const ull* aA = acc + p * 8;
        int sA = sidx + 64 * p, sB = sA + 32;
        float x0,x1,x2,x3;
        upk2(x0, x1, aA[0]); upk2(x2, x3, aA[1]);
        ((float4*)(ob + 8 * (size_t)sA))[0] = make_float4(x0, x1, x2, x3);
        upk2(x0, x1, aA[2]); upk2(x2, x3, aA[3]);
        ((float4*)(ob + 8 * (size_t)sA))[1] = make_float4(x0, x1, x2, x3);
        upk2(x0, x1, aA[4]); upk2(x2, x3, aA[5]);
        ((float4*)(ob + 8 * (size_t)sB))[0] = make_float4(x0, x1, x2, x3);
        upk2(x0, x1, aA[6]); upk2(x2, x3, aA[7]);
        ((float4*)(ob + 8 * (size_t)sB))[1] = make_float4(x0, x1, x2, x3);
    }
}

extern "C" void kernel_launch(void* const* d_in, const int* in_sizes, int n_in,
                              void* d_out, int out_size) {
    const float* f     = (const float*)d_in[0];
    const float* t     = (const float*)d_in[1];
    const float* W1    = (const float*)d_in[2];
    const float* b1    = (const float*)d_in[3];
    const float* W2    = (const float*)d_in[4];
    const float* b2    = (const float*)d_in[5];
    const float* W3    = (const float*)d_in[6];
    const float* b3    = (const float*)d_in[7];
    const float* mu    = (const float*)d_in[8];
    const float* alpha = (const float*)d_in[9];
    const float* beta  = (const float*)d_in[10];
    const float* gamma = (const float*)d_in[11];
    float* out = (float*)d_out;

    mlp_fused<<<128, 256>>>(f, W1, b1, W2, b2, W3);
    subspace_einsum<<<dim3(4, 64), 128>>>(t, mu, alpha, beta, gamma, b3, out);
}

// round 11
// speedup vs baseline: 1.3143x; 1.3143x over previous
#include <cuda_runtime.h>
#include <cstdint>

#define L2E 1.4426950408889634f
typedef unsigned long long ull;

// Scratch (static device globals — no runtime allocation)
__device__ float g_P1[4 * 64 * 512];     // split-K partials of f@W1
__device__ float g_P2[8 * 64 * 1024];    // split-K partials of relu(h1)@W2
__device__ float g_P3[16 * 64 * 512];    // split-K partials of relu(h2)@W3

// Grid-barrier state (returns to all-zero at end of every launch)
__device__ unsigned g_cnt[3]  = {0, 0, 0};
__device__ unsigned g_exit[3] = {0, 0, 0};

// ---- packed f32x2 helpers ---------------------------------------------------
__device__ __forceinline__ ull pk2(float lo, float hi) {
    ull r; asm("mov.b64 %0, {%1, %2};" : "=l"(r) : "f"(lo), "f"(hi)); return r;
}
__device__ __forceinline__ void upk2(float& lo, float& hi, ull v) {
    asm("mov.b64 {%0, %1}, %2;" : "=f"(lo), "=f"(hi) : "l"(v));
}
__device__ __forceinline__ ull fma2(ull a, ull b, ull c) {
    ull d; asm("fma.rn.f32x2 %0, %1, %2, %3;" : "=l"(d) : "l"(a), "l"(b), "l"(c)); return d;
}

// ---- software grid barrier (256 blocks, <=2/SM co-resident) -----------------
__device__ __forceinline__ void grid_bar(int i) {
    __syncthreads();
    if (threadIdx.x == 0) {
        __threadfence();
        atomicAdd(&g_cnt[i], 1u);
        while (*(volatile unsigned*)&g_cnt[i] < 256u) __nanosleep(40);
        __threadfence();
        unsigned e = atomicAdd(&g_exit[i], 1u);
        if (e == 255u) {                 // last exiter: everyone left the spin
            g_cnt[i] = 0; __threadfence(); g_exit[i] = 0;
        }
    }
    __syncthreads();
}

// ---------------------------------------------------------------------------
// GEMM tile: out[m][n0+n] = sum_{k in [k0,k0+KS)} Aval(m,k) * W[k][n]
// Aval = A[m][k] (raw) or relu(abias[k] + sum_p Aparts[p][m][k]).
// A staged once to smem; W double-buffered in 32-k chunks; f32x2 inner loop.
// ---------------------------------------------------------------------------
__device__ void gemm_tile(
    float* As, float (*Ws)[32][32],
    const float* __restrict__ A,
    const float* __restrict__ Aparts, int nparts,
    const float* __restrict__ abias,
    int K_full, int KS,
    const float* __restrict__ W, int N,
    int n0, int k0,
    float* __restrict__ out)
{
    const int tid = threadIdx.x;

    // Stage A tile [64 x KS]
    const int KQ4 = KS / 4;
    for (int f = tid; f < 64 * KQ4; f += 256) {
        int m = f / KQ4, kq = f - m * KQ4;
        int k = k0 + 4 * kq;
        float4 v;
        if (A) {
            v = *(const float4*)(A + (size_t)m * K_full + k);
        } else {
            v = *(const float4*)(abias + k);
            for (int p = 0; p < nparts; p++) {
                float4 w = *(const float4*)(Aparts + (size_t)p * 64 * K_full
                                            + (size_t)m * K_full + k);
                v.x += w.x; v.y += w.y; v.z += w.z; v.w += w.w;
            }
            v.x = fmaxf(v.x, 0.f); v.y = fmaxf(v.y, 0.f);
            v.z = fmaxf(v.z, 0.f); v.w = fmaxf(v.w, 0.f);
        }
        *(float4*)&As[m * KS + 4 * kq] = v;
    }

    const int iw = tid >> 3, nn = (tid & 7) * 4;
    {
        float4 w = *(const float4*)(W + (size_t)(k0 + iw) * N + n0 + nn);
        *(float4*)&Ws[0][iw][nn] = w;
    }
    __syncthreads();

    const int n  = tid & 31;
    const int mb = (tid >> 5) * 8;
    ull acc2[8] = {0,0,0,0,0,0,0,0};

    const int NC = KS / 32;
    for (int c = 0; c < NC; c++) {
        if (c + 1 < NC) {
            float4 w = *(const float4*)(W + (size_t)(k0 + (c+1)*32 + iw) * N + n0 + nn);
            *(float4*)&Ws[(c + 1) & 1][iw][nn] = w;
        }
        const float* wsb = &Ws[c & 1][0][0];
        const int kc = c * 32;
        #pragma unroll
        for (int k = 0; k < 32; k += 4) {
            float w0 = wsb[(k+0)*32 + n], w1 = wsb[(k+1)*32 + n];
            float w2 = wsb[(k+2)*32 + n], w3 = wsb[(k+3)*32 + n];
            ull wA = pk2(w0, w1), wB = pk2(w2, w3);
            #pragma unroll
            for (int q = 0; q < 8; q++) {
                ulonglong2 av = *(const ulonglong2*)&As[(mb + q) * KS + kc + k];
                acc2[q] = fma2(av.x, wA, acc2[q]);
                acc2[q] = fma2(av.y, wB, acc2[q]);
            }
        }
        __syncthreads();
    }

    #pragma unroll
    for (int q = 0; q < 8; q++) {
        float lo, hi; upk2(lo, hi, acc2[q]);
        out[(size_t)(mb + q) * N + n0 + n] = lo + hi;
    }
}

// ---------------------------------------------------------------------------
// ONE kernel: 3 MLP phases + einsum. Grid 256 x 256 thr.
// __launch_bounds__(256,2) -> <=128 regs: NO spills (R8's fatal mistake was
// capping at 64), co-residency guaranteed (2/SM x 148 = 296 >= 256).
// ---------------------------------------------------------------------------
__global__ void __launch_bounds__(256, 2) fused_all(
    const float* __restrict__ f,  const float* __restrict__ t,
    const float* __restrict__ W1, const float* __restrict__ b1,
    const float* __restrict__ W2, const float* __restrict__ b2,
    const float* __restrict__ W3, const float* __restrict__ b3,
    const float* __restrict__ mu, const float* __restrict__ alpha,
    const float* __restrict__ beta, const float* __restrict__ gamma,
    float* __restrict__ out)
{
    __shared__ float As[64 * 64];        // 16KB
    __shared__ float Ws[2][32][32];      // 8KB
    __shared__ float s_p[64], s_q[64], s_r[64], s_be[64], s_ga[64];
    __shared__ float4 s_we[64], s_wo[64];

    const int bid = blockIdx.x;
    const int tid = threadIdx.x;

    // Phase 1 (64 units): P1[4] = f @ W1  (K=128, KS=32, n-tile 32)
    if (bid < 64) {
        int n0 = (bid & 15) * 32, ks = bid >> 4;
        gemm_tile(As, Ws, f, nullptr, 0, nullptr, 128, 32, W1, 512,
                  n0, ks * 32, g_P1 + (size_t)ks * 64 * 512);
    }
    grid_bar(0);

    // Phase 2 (256 units): P2[8] = relu(b1 + sum4 P1) @ W2  (K=512, KS=64)
    {
        int n0 = (bid & 31) * 32, ks = bid >> 5;
        gemm_tile(As, Ws, nullptr, g_P1, 4, b1, 512, 64, W2, 1024,
                  n0, ks * 64, g_P2 + (size_t)ks * 64 * 1024);
    }
    grid_bar(1);

    // Phase 3 (256 units): P3[16] = relu(b2 + sum8 P2) @ W3  (K=1024, KS=64)
    {
        int n0 = (bid & 15) * 32, ks = bid >> 4;
        gemm_tile(As, Ws, nullptr, g_P2, 8, b2, 1024, 64, W3, 512,
                  n0, ks * 64, g_P3 + (size_t)ks * 64 * 512);
    }
    grid_bar(2);

    // ---- Einsum: E=4 elems/thread (2 f32x2 pairs). block -> (batch, s-chunk)
    const int b  = bid >> 2;     // batch 0..63
    const int sc = bid & 3;      // s-chunk 0..3 (1024 elems each)

    if (tid < 64) {
        float al = alpha[tid], m = mu[tid];
        float a2 = al * al * L2E;
        s_p[tid]  = -a2;
        s_q[tid]  = 2.f * a2 * m;
        s_r[tid]  = -a2 * m * m;
        s_be[tid] = beta[tid];
        s_ga[tid] = gamma[tid];
    }
    // omega[b] = b3 + sum of 16 deterministic split-K partials
    for (int j = tid; j < 512; j += 256) {
        float v = b3[j];
        #pragma unroll
        for (int p = 0; p < 16; p++)
            v += g_P3[(size_t)p * 64 * 512 + (size_t)b * 512 + j];
        int row = j >> 2, r = j & 3;
        int nb = row & 63;
        float* dst = (row < 64) ? (float*)&s_we[nb] : (float*)&s_wo[nb];
        dst[r] = v;
    }
    __syncthreads();

    const float* tb = t + (size_t)b * 4096;
    const int s0 = sc * 1024 + tid;
    // pair A: elems (s0, s0+256); pair B: (s0+512, s0+768)
    float tA0 = tb[s0],       tA1 = tb[s0 + 256];
    float tB0 = tb[s0 + 512], tB1 = tb[s0 + 768];
    const ull ttA = pk2(tA0, tA1), tqA = pk2(tA0 * tA0, tA1 * tA1);
    const ull ttB = pk2(tB0, tB1), tqB = pk2(tB0 * tB0, tB1 * tB1);

    // acc[P*8 + {0..3}] = pair-P lo elem {(r0,r1)e,(r2,r3)e,(r0,r1)o,(r2,r3)o}
    //        + {4..7}   = pair-P hi elem
    ull acc[16];
    #pragma unroll
    for (int j = 0; j < 16; j++) acc[j] = 0ull;

    #pragma unroll 4
    for (int nb = 0; nb < 64; nb++) {
        float p = s_p[nb], q = s_q[nb], r = s_r[nb];
        float be = s_be[nb], ga = s_ga[nb];
        ull pp = pk2(p, p), qq = pk2(q, q), rr = pk2(r, r);
        ull bb = pk2(be, be), gg = pk2(ga, ga);
        ulonglong2 we = *(const ulonglong2*)&s_we[nb];  // (w0,w1)(w2,w3)
        ulonglong2 wo = *(const ulonglong2*)&s_wo[nb];

        #pragma unroll
        for (int P = 0; P < 2; P++) {
            const ull tt = P ? ttB : ttA;
            const ull tq = P ? tqB : tqA;

            ull a = fma2(pp, tq, fma2(qq, tt, rr));
            float a0, a1; upk2(a0, a1, a);
            float e0, e1;
            asm("ex2.approx.f32 %0, %1;" : "=f"(e0) : "f"(a0));
            asm("ex2.approx.f32 %0, %1;" : "=f"(e1) : "f"(a1));

            ull ca = fma2(bb, tt, gg);
            float c0, c1f; upk2(c0, c1f, ca);
            float h0 = e0 * __cosf(c0);
            float h1 = e1 * __cosf(c1f);
            ull hh0 = pk2(h0, h0), hh1 = pk2(h1, h1);

            ull* ac = acc + P * 8;
            ac[0] = fma2(hh0, we.x, ac[0]);
            ac[1] = fma2(hh0, we.y, ac[1]);
            ac[2] = fma2(hh0, wo.x, ac[2]);
            ac[3] = fma2(hh0, wo.y, ac[3]);
            ac[4] = fma2(hh1, we.x, ac[4]);
            ac[5] = fma2(hh1, we.y, ac[5]);
            ac[6] = fma2(hh1, wo.x, ac[6]);
            ac[7] = fma2(hh1, wo.y, ac[7]);
        }
    }

    float* ob = out + (size_t)b * 32768;
    #pragma unroll
    for (int P = 0; P < 2; P++) {
        const ull* ac = acc + P * 8;
        int sL = s0 + P * 512, sH = sL + 256;
        float x0, x1, x2, x3;
        upk2(x0, x1, ac[0]); upk2(x2, x3, ac[1]);
        ((float4*)(ob + 8 * (size_t)sL))[0] = make_float4(x0, x1, x2, x3);
        upk2(x0, x1, ac[2]); upk2(x2, x3, ac[3]);
        ((float4*)(ob + 8 * (size_t)sL))[1] = make_float4(x0, x1, x2, x3);
        upk2(x0, x1, ac[4]); upk2(x2, x3, ac[5]);
        ((float4*)(ob + 8 * (size_t)sH))[0] = make_float4(x0, x1, x2, x3);
        upk2(x0, x1, ac[6]); upk2(x2, x3, ac[7]);
        ((float4*)(ob + 8 * (size_t)sH))[1] = make_float4(x0, x1, x2, x3);
    }
}

extern "C" void kernel_launch(void* const* d_in, const int* in_sizes, int n_in,
                              void* d_out, int out_size) {
    const float* f     = (const float*)d_in[0];
    const float* t     = (const float*)d_in[1];
    const float* W1    = (const float*)d_in[2];
    const float* b1    = (const float*)d_in[3];
    const float* W2    = (const float*)d_in[4];
    const float* b2    = (const float*)d_in[5];
    const float* W3    = (const float*)d_in[6];
    const float* b3    = (const float*)d_in[7];
    const float* mu    = (const float*)d_in[8];
    const float* alpha = (const float*)d_in[9];
    const float* beta  = (const float*)d_in[10];
    const float* gamma = (const float*)d_in[11];
    float* out = (float*)d_out;

    fused_all<<<256, 256>>>(f, t, W1, b1, W2, b2, W3, b3,
                            mu, alpha, beta, gamma, out);
}

// round 14
// speedup vs baseline: 1.3188x; 1.0034x over previous
#include <cuda_runtime.h>
#include <cstdint>

#define L2E 1.4426950408889634f
typedef unsigned long long ull;

// Scratch (static device globals — no runtime allocation)
__device__ float g_P1[4 * 64 * 512];     // split-K partials of f@W1
__device__ float g_P2[8 * 64 * 1024];    // split-K partials of relu(h1)@W2
__device__ float g_P3[16 * 64 * 512];    // split-K partials of relu(h2)@W3

// Grid-barrier state (returns to all-zero at end of every launch)
__device__ unsigned g_cnt[3]  = {0, 0, 0};
__device__ unsigned g_exit[3] = {0, 0, 0};

// ---- packed f32x2 helpers ---------------------------------------------------
__device__ __forceinline__ ull pk2(float lo, float hi) {
    ull r; asm("mov.b64 %0, {%1, %2};" : "=l"(r) : "f"(lo), "f"(hi)); return r;
}
__device__ __forceinline__ void upk2(float& lo, float& hi, ull v) {
    asm("mov.b64 {%0, %1}, %2;" : "=f"(lo), "=f"(hi) : "l"(v));
}
__device__ __forceinline__ ull fma2(ull a, ull b, ull c) {
    ull d; asm("fma.rn.f32x2 %0, %1, %2, %3;" : "=l"(d) : "l"(a), "l"(b), "l"(c)); return d;
}

// ---- software grid barrier (256 blocks, <=2/SM co-resident) -----------------
__device__ __forceinline__ void grid_bar(int i) {
    __syncthreads();
    if (threadIdx.x == 0) {
        __threadfence();
        atomicAdd(&g_cnt[i], 1u);
        while (*(volatile unsigned*)&g_cnt[i] < 256u) __nanosleep(40);
        __threadfence();
        unsigned e = atomicAdd(&g_exit[i], 1u);
        if (e == 255u) {                 // last exiter: everyone left the spin
            g_cnt[i] = 0; __threadfence(); g_exit[i] = 0;
        }
    }
    __syncthreads();
}

// ---------------------------------------------------------------------------
// GEMM tile: out[m][n0+n] = sum_{k in [k0,k0+KS)} Aval(m,k) * W[k][n]
// Aval = A[m][k] (raw) or relu(abias[k] + sum_p Aparts[p][m][k]).
// A staged once to smem; W double-buffered in 32-k chunks; f32x2 inner loop.
// ---------------------------------------------------------------------------
__device__ void gemm_tile(
    float* As, float (*Ws)[32][32],
    const float* __restrict__ A,
    const float* __restrict__ Aparts, int nparts,
    const float* __restrict__ abias,
    int K_full, int KS,
    const float* __restrict__ W, int N,
    int n0, int k0,
    float* __restrict__ out)
{
    const int tid = threadIdx.x;

    // Stage A tile [64 x KS]
    const int KQ4 = KS / 4;
    for (int f = tid; f < 64 * KQ4; f += 256) {
        int m = f / KQ4, kq = f - m * KQ4;
        int k = k0 + 4 * kq;
        float4 v;
        if (A) {
            v = *(const float4*)(A + (size_t)m * K_full + k);
        } else {
            v = *(const float4*)(abias + k);
            for (int p = 0; p < nparts; p++) {
                float4 w = *(const float4*)(Aparts + (size_t)p * 64 * K_full
                                            + (size_t)m * K_full + k);
                v.x += w.x; v.y += w.y; v.z += w.z; v.w += w.w;
            }
            v.x = fmaxf(v.x, 0.f); v.y = fmaxf(v.y, 0.f);
            v.z = fmaxf(v.z, 0.f); v.w = fmaxf(v.w, 0.f);
        }
        *(float4*)&As[m * KS + 4 * kq] = v;
    }

    const int iw = tid >> 3, nn = (tid & 7) * 4;
    {
        float4 w = *(const float4*)(W + (size_t)(k0 + iw) * N + n0 + nn);
        *(float4*)&Ws[0][iw][nn] = w;
    }
    __syncthreads();

    const int n  = tid & 31;
    const int mb = (tid >> 5) * 8;
    ull acc2[8] = {0,0,0,0,0,0,0,0};

    const int NC = KS / 32;
    for (int c = 0; c < NC; c++) {
        if (c + 1 < NC) {
            float4 w = *(const float4*)(W + (size_t)(k0 + (c+1)*32 + iw) * N + n0 + nn);
            *(float4*)&Ws[(c + 1) & 1][iw][nn] = w;
        }
        const float* wsb = &Ws[c & 1][0][0];
        const int kc = c * 32;
        #pragma unroll
        for (int k = 0; k < 32; k += 4) {
            float w0 = wsb[(k+0)*32 + n], w1 = wsb[(k+1)*32 + n];
            float w2 = wsb[(k+2)*32 + n], w3 = wsb[(k+3)*32 + n];
            ull wA = pk2(w0, w1), wB = pk2(w2, w3);
            #pragma unroll
            for (int q = 0; q < 8; q++) {
                ulonglong2 av = *(const ulonglong2*)&As[(mb + q) * KS + kc + k];
                acc2[q] = fma2(av.x, wA, acc2[q]);
                acc2[q] = fma2(av.y, wB, acc2[q]);
            }
        }
        __syncthreads();
    }

    #pragma unroll
    for (int q = 0; q < 8; q++) {
        float lo, hi; upk2(lo, hi, acc2[q]);
        out[(size_t)(mb + q) * N + n0 + n] = lo + hi;
    }
}

// ---------------------------------------------------------------------------
// MLP: 3 phases in one persistent launch (grid 256, 2 barriers).
// ---------------------------------------------------------------------------
__global__ void __launch_bounds__(256, 2) mlp_fused(
    const float* __restrict__ f,
    const float* __restrict__ W1, const float* __restrict__ b1,
    const float* __restrict__ W2, const float* __restrict__ b2,
    const float* __restrict__ W3)
{
    __shared__ float As[64 * 64];        // 16KB
    __shared__ float Ws[2][32][32];      // 8KB

    const int bid = blockIdx.x;

    // Phase 1 (64 units): P1[4] = f @ W1  (K=128, KS=32, n-tile 32)
    if (bid < 64) {
        int n0 = (bid & 15) * 32, ks = bid >> 4;
        gemm_tile(As, Ws, f, nullptr, 0, nullptr, 128, 32, W1, 512,
                  n0, ks * 32, g_P1 + (size_t)ks * 64 * 512);
    }
    grid_bar(0);

    // Phase 2 (256 units): P2[8] = relu(b1 + sum4 P1) @ W2  (K=512, KS=64)
    {
        int n0 = (bid & 31) * 32, ks = bid >> 5;
        gemm_tile(As, Ws, nullptr, g_P1, 4, b1, 512, 64, W2, 1024,
                  n0, ks * 64, g_P2 + (size_t)ks * 64 * 1024);
    }
    grid_bar(1);

    // Phase 3 (256 units): P3[16] = relu(b2 + sum8 P2) @ W3  (K=1024, KS=64)
    {
        int n0 = (bid & 15) * 32, ks = bid >> 4;
        gemm_tile(As, Ws, nullptr, g_P2, 8, b2, 1024, 64, W3, 512,
                  n0, ks * 64, g_P3 + (size_t)ks * 64 * 512);
    }
}

// ---------------------------------------------------------------------------
// Einsum standalone: E=4 elems/thread (2 f32x2 pairs), 128 thr,
// grid (8, 64) = 512 blocks — single fully-resident wave, no spills.
// ---------------------------------------------------------------------------
__global__ void __launch_bounds__(128) subspace_einsum(
    const float* __restrict__ t,
    const float* __restrict__ mu, const float* __restrict__ alpha,
    const float* __restrict__ beta, const float* __restrict__ gamma,
    const float* __restrict__ b3,
    float* __restrict__ out)
{
    __shared__ float s_p[64], s_q[64], s_r[64], s_be[64], s_ga[64];
    __shared__ float4 s_we[64], s_wo[64];

    const int tid = threadIdx.x;
    const int b   = blockIdx.y;
    const int sc  = blockIdx.x;

    if (tid < 64) {
        float al = alpha[tid], m = mu[tid];
        float a2 = al * al * L2E;
        s_p[tid]  = -a2;
        s_q[tid]  = 2.f * a2 * m;
        s_r[tid]  = -a2 * m * m;
        s_be[tid] = beta[tid];
        s_ga[tid] = gamma[tid];
    }
    // omega[b] = b3 + sum of 16 deterministic split-K partials
    for (int j = tid; j < 512; j += 128) {
        float v = b3[j];
        #pragma unroll
        for (int p = 0; p < 16; p++)
            v += g_P3[(size_t)p * 64 * 512 + (size_t)b * 512 + j];
        int row = j >> 2, r = j & 3;
        int nb = row & 63;
        float* dst = (row < 64) ? (float*)&s_we[nb] : (float*)&s_wo[nb];
        dst[r] = v;
    }
    __syncthreads();

    const float* tb = t + (size_t)b * 4096;
    const int s0 = sc * 512 + tid;
    // pair A: elems (s0, s0+128); pair B: (s0+256, s0+384)
    float tA0 = tb[s0],       tA1 = tb[s0 + 128];
    float tB0 = tb[s0 + 256], tB1 = tb[s0 + 384];
    const ull ttA = pk2(tA0, tA1), tqA = pk2(tA0 * tA0, tA1 * tA1);
    const ull ttB = pk2(tB0, tB1), tqB = pk2(tB0 * tB0, tB1 * tB1);

    // acc[P*8+{0..3}] = pair-P lo elem {(r0,r1)e,(r2,r3)e,(r0,r1)o,(r2,r3)o};
    //       +{4..7}   = pair-P hi elem
    ull acc[16];
    #pragma unroll
    for (int j = 0; j < 16; j++) acc[j] = 0ull;

    #pragma unroll 4
    for (int nb = 0; nb < 64; nb++) {
        float p = s_p[nb], q = s_q[nb], r = s_r[nb];
        float be = s_be[nb], ga = s_ga[nb];
        ull pp = pk2(p, p), qq = pk2(q, q), rr = pk2(r, r);
        ull bb = pk2(be, be), gg = pk2(ga, ga);
        ulonglong2 we = *(const ulonglong2*)&s_we[nb];  // (w0,w1)(w2,w3)
        ulonglong2 wo = *(const ulonglong2*)&s_wo[nb];

        #pragma unroll
        for (int P = 0; P < 2; P++) {
            const ull tt = P ? ttB : ttA;
            const ull tq = P ? tqB : tqA;

            ull a = fma2(pp, tq, fma2(qq, tt, rr));
            float a0, a1; upk2(a0, a1, a);
            float e0, e1;
            asm("ex2.approx.f32 %0, %1;" : "=f"(e0) : "f"(a0));
            asm("ex2.approx.f32 %0, %1;" : "=f"(e1) : "f"(a1));

            ull ca = fma2(bb, tt, gg);
            float c0, c1f; upk2(c0, c1f, ca);
            float h0 = e0 * __cosf(c0);
            float h1 = e1 * __cosf(c1f);
            ull hh0 = pk2(h0, h0), hh1 = pk2(h1, h1);

            ull* ac = acc + P * 8;
            ac[0] = fma2(hh0, we.x, ac[0]);
            ac[1] = fma2(hh0, we.y, ac[1]);
            ac[2] = fma2(hh0, wo.x, ac[2]);
            ac[3] = fma2(hh0, wo.y, ac[3]);
            ac[4] = fma2(hh1, we.x, ac[4]);
            ac[5] = fma2(hh1, we.y, ac[5]);
            ac[6] = fma2(hh1, wo.x, ac[6]);
            ac[7] = fma2(hh1, wo.y, ac[7]);
        }
    }

    float* ob = out + (size_t)b * 32768;
    #pragma unroll
    for (int P = 0; P < 2; P++) {
        const ull* ac = acc + P * 8;
        int sL = s0 + P * 256, sH = sL + 128;
        float x0, x1, x2, x3;
        upk2(x0, x1, ac[0]); upk2(x2, x3, ac[1]);
        ((float4*)(ob + 8 * (size_t)sL))[0] = make_float4(x0, x1, x2, x3);
        upk2(x0, x1, ac[2]); upk2(x2, x3, ac[3]);
        ((float4*)(ob + 8 * (size_t)sL))[1] = make_float4(x0, x1, x2, x3);
        upk2(x0, x1, ac[4]); upk2(x2, x3, ac[5]);
        ((float4*)(ob + 8 * (size_t)sH))[0] = make_float4(x0, x1, x2, x3);
        upk2(x0, x1, ac[6]); upk2(x2, x3, ac[7]);
        ((float4*)(ob + 8 * (size_t)sH))[1] = make_float4(x0, x1, x2, x3);
    }
}

extern "C" void kernel_launch(void* const* d_in, const int* in_sizes, int n_in,
                              void* d_out, int out_size) {
    const float* f     = (const float*)d_in[0];
    const float* t     = (const float*)d_in[1];
    const float* W1    = (const float*)d_in[2];
    const float* b1    = (const float*)d_in[3];
    const float* W2    = (const float*)d_in[4];
    const float* b2    = (const float*)d_in[5];
    const float* W3    = (const float*)d_in[6];
    const float* b3    = (const float*)d_in[7];
    const float* mu    = (const float*)d_in[8];
    const float* alpha = (const float*)d_in[9];
    const float* beta  = (const float*)d_in[10];
    const float* gamma = (const float*)d_in[11];
    float* out = (float*)d_out;

    mlp_fused<<<256, 256>>>(f, W1, b1, W2, b2, W3);
    subspace_einsum<<<dim3(8, 64), 128>>>(t, mu, alpha, beta, gamma, b3, out);
}